// round 13
// baseline (speedup 1.0000x reference)
#include <cuda_runtime.h>
#include <cstdint>
#include <math.h>

#define BB 128
#define SS 512
#define EE 192
#define TT (BB*SS)
#define QD 48
#define NH 3
#define HD 16

__device__ float g_xn[TT][EE];
__device__ float g_qkv[2][TT][144];
__device__ float g_conv[TT][96];
__device__ float g_att[TT][96];
__device__ float g_x1[TT][EE];
__device__ float g_x1n[TT][EE];

__device__ __forceinline__ unsigned f2tf32(float v) {
    unsigned u;
    asm("cvt.rna.tf32.f32 %0, %1;" : "=r"(u) : "f"(v));
    return u;
}
__device__ __forceinline__ float tf32f(float v) { return __uint_as_float(f2tf32(v)); }

__device__ __forceinline__ void mma_tf32(float4& c, const float4& a, const float2& b) {
    asm volatile(
        "mma.sync.aligned.m16n8k8.row.col.f32.tf32.tf32.f32 "
        "{%0,%1,%2,%3},{%4,%5,%6,%7},{%8,%9},{%0,%1,%2,%3};"
        : "+f"(c.x), "+f"(c.y), "+f"(c.z), "+f"(c.w)
        : "r"(__float_as_uint(a.x)), "r"(__float_as_uint(a.y)),
          "r"(__float_as_uint(a.z)), "r"(__float_as_uint(a.w)),
          "r"(__float_as_uint(b.x)), "r"(__float_as_uint(b.y)));
}

__device__ __forceinline__ void cpa16(unsigned int dst, const void* src) {
    asm volatile("cp.async.cg.shared.global [%0], [%1], 16;" :: "r"(dst), "l"(src) : "memory");
}

// ---------------- K1: LN1 + feature-conv ----------------
__global__ __launch_bounds__(256) void k1_ln_conv(
    const float* __restrict__ x,
    const float* __restrict__ ln1g, const float* __restrict__ ln1b,
    const float* __restrict__ convw)
{
    __shared__ float sx[8][192];

    int tid = threadIdx.x;
    int warp = tid >> 5, lane = tid & 31;
    int t = blockIdx.x * 8 + warp;

    float v[6];
    float sum = 0.f, sq = 0.f;
    #pragma unroll
    for (int i = 0; i < 6; i++) {
        v[i] = x[(size_t)t*EE + lane + i*32];
        sum += v[i]; sq += v[i]*v[i];
    }
    #pragma unroll
    for (int o = 16; o > 0; o >>= 1) {
        sum += __shfl_xor_sync(0xffffffffu, sum, o);
        sq  += __shfl_xor_sync(0xffffffffu, sq,  o);
    }
    float mean = sum * (1.f/192.f);
    float var  = sq * (1.f/192.f) - mean*mean;
    float rstd = rsqrtf(var + 1e-6f);
    #pragma unroll
    for (int i = 0; i < 6; i++) {
        int f = lane + i*32;
        float xn = (v[i] - mean) * rstd * ln1g[f] + ln1b[f];
        sx[warp][f] = xn;
        g_xn[t][f] = xn;
    }
    __syncwarp();

    int c = t & 3;
    float cw[15];
    #pragma unroll
    for (int k = 0; k < 15; k++) cw[k] = convw[c*15 + k];
    const float* xw = &sx[warp][48];
    #pragma unroll
    for (int r = 0; r < 3; r++) {
        int w = lane + r*32;
        float acc = 0.f;
        #pragma unroll
        for (int k = 0; k < 15; k++) {
            int idx = w + k - 7;
            if (idx >= 0 && idx < 96) acc += cw[k] * xw[idx];
        }
        g_conv[t][w] = acc;
    }
}

// ---------------- K1b: QKV via tf32 mma ----------------
#define K1B_SAS 100
#define K1B_SBS 52
#define K1B_SMEM ((64*K1B_SAS + 288*K1B_SBS + 288) * 4)

__global__ __launch_bounds__(256) void k1b_qkv_mma(
    const float* __restrict__ accw, const float* __restrict__ accb,
    const float* __restrict__ gyrw, const float* __restrict__ gyrb)
{
    extern __shared__ float smm[];
    float* sA    = smm;
    float* sB    = smm + 64*K1B_SAS;
    float* sbias = smm + 64*K1B_SAS + 288*K1B_SBS;

    int tid = threadIdx.x;
    int t0 = blockIdx.x * 64;

    for (int cc = tid; cc < 288*12; cc += 256) {
        int row = cc / 12, q = cc % 12;
        const float* src = (row < 144) ? &accw[row*48 + q*4] : &gyrw[(row-144)*48 + q*4];
        *(float4*)&sB[row*K1B_SBS + q*4] = *(const float4*)src;
    }
    for (int j = tid; j < 288; j += 256)
        sbias[j] = (j < 144) ? accb[j] : gyrb[j-144];

    for (int cc = tid; cc < 64*24; cc += 256) {
        int row = cc / 24, q = cc % 24;
        int srcc = (q < 12) ? q*4 : 96 + (q-12)*4;
        *(float4*)&sA[row*K1B_SAS + q*4] = *(const float4*)&g_xn[t0+row][srcc];
    }
    __syncthreads();

    int warp = tid >> 5, lane = tid & 31;
    int g = lane >> 2, t4 = lane & 3;
    int wm = warp & 1, wn = warp >> 1;
    int koff = (wn >= 2) ? 48 : 0;

    float4 acc[2][9];
    #pragma unroll
    for (int mi = 0; mi < 2; mi++)
        #pragma unroll
        for (int ni = 0; ni < 9; ni++)
            acc[mi][ni] = make_float4(0.f,0.f,0.f,0.f);

    #pragma unroll
    for (int kt = 0; kt < 6; kt++) {
        float4 av[2];
        #pragma unroll
        for (int mi = 0; mi < 2; mi++) {
            int r0 = wm*32 + mi*16 + g;
            int kk = koff + kt*8 + t4;
            av[mi].x = sA[r0*K1B_SAS + kk];
            av[mi].y = sA[(r0+8)*K1B_SAS + kk];
            av[mi].z = sA[r0*K1B_SAS + kk + 4];
            av[mi].w = sA[(r0+8)*K1B_SAS + kk + 4];
        }
        #pragma unroll
        for (int ni = 0; ni < 9; ni++) {
            int n = wn*72 + ni*8 + g;
            float2 bf;
            bf.x = sB[n*K1B_SBS + kt*8 + t4];
            bf.y = sB[n*K1B_SBS + kt*8 + t4 + 4];
            mma_tf32(acc[0][ni], av[0], bf);
            mma_tf32(acc[1][ni], av[1], bf);
        }
    }

    #pragma unroll
    for (int mi = 0; mi < 2; mi++) {
        #pragma unroll
        for (int ni = 0; ni < 9; ni++) {
            int m0 = t0 + wm*32 + mi*16 + g;
            int n  = wn*72 + ni*8 + t4*2;
            int br = (n >= 144);
            int col = n - br*144;
            float b0 = sbias[n], b1 = sbias[n+1];
            *(float2*)&g_qkv[br][m0][col]   = make_float2(acc[mi][ni].x + b0, acc[mi][ni].y + b1);
            *(float2*)&g_qkv[br][m0+8][col] = make_float2(acc[mi][ni].z + b0, acc[mi][ni].w + b1);
        }
    }
}

// ---------------- K2: tensor-core attention ----------------
#define K2_SMEM ((8192 + 8192 + 8*16*68) * 4)
#define QSCALE (0.25f * 1.44269504088896340736f)

__global__ __launch_bounds__(256) void k2_attn_mma()
{
    extern __shared__ float sm[];
    float* sK = sm;
    float* sV = sm + 8192;
    float* sP = sm + 16384;

    int tid = threadIdx.x;
    int qb   = blockIdx.x & 1;
    int rest = blockIdx.x >> 1;
    int h  = rest % NH;  rest /= NH;
    int b  = rest % BB;
    int br = rest / BB;
    int tbase = b * SS;

    for (int idx = tid; idx < SS*HD; idx += 256) {
        int key = idx >> 4, d = idx & 15;
        float kv = g_qkv[br][tbase+key][48 + h*16 + d];
        float vv = g_qkv[br][tbase+key][96 + h*16 + d];
        int laneK = (key & 7)*4 + (d & 3);
        sK[(((key>>3)*2 + (d>>3))*32 + laneK)*2 + ((d>>2)&1)] = tf32f(kv);
        int laneV = (d & 7)*4 + (key & 3);
        sV[(((key>>3)*2 + (d>>3))*32 + laneV)*2 + ((key>>2)&1)] = tf32f(vv);
    }

    int wq = tid >> 5, lane = tid & 31;
    int g = lane >> 2, t4 = lane & 3;
    int qbase = tbase + qb*256 + wq*32;

    float4 qa[2][2];
    #pragma unroll
    for (int c = 0; c < 2; c++) {
        const float* qr0 = &g_qkv[br][qbase + c*16 + g][h*16];
        const float* qr1 = &g_qkv[br][qbase + c*16 + g + 8][h*16];
        #pragma unroll
        for (int kt = 0; kt < 2; kt++) {
            qa[c][kt].x = tf32f(qr0[kt*8 + t4]     * QSCALE);
            qa[c][kt].y = tf32f(qr1[kt*8 + t4]     * QSCALE);
            qa[c][kt].z = tf32f(qr0[kt*8 + t4 + 4] * QSCALE);
            qa[c][kt].w = tf32f(qr1[kt*8 + t4 + 4] * QSCALE);
        }
    }
    __syncthreads();

    float4 oacc[2][2];
    float l0[2], l1[2];
    #pragma unroll
    for (int c = 0; c < 2; c++) {
        oacc[c][0] = make_float4(0.f,0.f,0.f,0.f);
        oacc[c][1] = make_float4(0.f,0.f,0.f,0.f);
        l0[c] = 0.f; l1[c] = 0.f;
    }
    float* sPw = sP + wq*16*68;

    for (int kb = 0; kb < 8; kb++) {
        #pragma unroll
        for (int c = 0; c < 2; c++) {
            float4 sacc[8];
            #pragma unroll
            for (int ni = 0; ni < 8; ni++) sacc[ni] = make_float4(0.f,0.f,0.f,0.f);

            #pragma unroll
            for (int ni = 0; ni < 8; ni++) {
                int nt = kb*8 + ni;
                mma_tf32(sacc[ni], qa[c][0], *(const float2*)&sK[((nt*2+0)*32 + lane)*2]);
                mma_tf32(sacc[ni], qa[c][1], *(const float2*)&sK[((nt*2+1)*32 + lane)*2]);
            }
            #pragma unroll
            for (int ni = 0; ni < 8; ni++) {
                float px = exp2f(sacc[ni].x), py = exp2f(sacc[ni].y);
                float pz = exp2f(sacc[ni].z), pw = exp2f(sacc[ni].w);
                l0[c] += px + py; l1[c] += pz + pw;
                float2 hi = make_float2(tf32f(px), tf32f(py));
                float2 lo = make_float2(tf32f(pz), tf32f(pw));
                *(float2*)&sPw[ g   *68 + ni*8 + 2*t4] = hi;
                *(float2*)&sPw[(g+8)*68 + ni*8 + 2*t4] = lo;
            }
            __syncwarp();
            #pragma unroll
            for (int kt2 = 0; kt2 < 8; kt2++) {
                float4 af;
                af.x = sPw[ g   *68 + kt2*8 + t4];
                af.y = sPw[(g+8)*68 + kt2*8 + t4];
                af.z = sPw[ g   *68 + kt2*8 + t4 + 4];
                af.w = sPw[(g+8)*68 + kt2*8 + t4 + 4];
                int ktg = kb*8 + kt2;
                mma_tf32(oacc[c][0], af, *(const float2*)&sV[((ktg*2+0)*32 + lane)*2]);
                mma_tf32(oacc[c][1], af, *(const float2*)&sV[((ktg*2+1)*32 + lane)*2]);
            }
            __syncwarp();
        }
    }

    #pragma unroll
    for (int c = 0; c < 2; c++) {
        float a0 = l0[c], a1 = l1[c];
        a0 += __shfl_xor_sync(0xffffffffu, a0, 1);
        a0 += __shfl_xor_sync(0xffffffffu, a0, 2);
        a1 += __shfl_xor_sync(0xffffffffu, a1, 1);
        a1 += __shfl_xor_sync(0xffffffffu, a1, 2);
        float i0 = 1.f / a0, i1 = 1.f / a1;
        int q0 = qbase + c*16;
        #pragma unroll
        for (int nt = 0; nt < 2; nt++) {
            int col = br*48 + h*16 + nt*8 + 2*t4;
            *(float2*)&g_att[q0+g  ][col] = make_float2(oacc[c][nt].x*i0, oacc[c][nt].y*i0);
            *(float2*)&g_att[q0+g+8][col] = make_float2(oacc[c][nt].z*i1, oacc[c][nt].w*i1);
        }
    }
}

// ---------------- K3: proj mma + concat + res + LN2 ----------------
#define K3_SAS 100
#define K3_SPS 100
#define K3_SBS 52
#define K3_SMEM ((64*K3_SAS + 64*K3_SPS + 96*K3_SBS + 96) * 4)

__global__ __launch_bounds__(256) void k3_proj_ln2_mma(
    const float* __restrict__ x,
    const float* __restrict__ accwo, const float* __restrict__ accbo,
    const float* __restrict__ gyrwo, const float* __restrict__ gyrbo,
    const float* __restrict__ ln2g, const float* __restrict__ ln2b)
{
    extern __shared__ float smm[];
    float* sA    = smm;
    float* sPj   = smm + 64*K3_SAS;
    float* sW    = smm + 64*K3_SAS + 64*K3_SPS;
    float* sbias = sW + 96*K3_SBS;

    int tid = threadIdx.x;
    int t0 = blockIdx.x * 64;

    for (int cc = tid; cc < 96*12; cc += 256) {
        int row = cc / 12, q = cc % 12;
        const float* src = (row < 48) ? &accwo[row*48 + q*4] : &gyrwo[(row-48)*48 + q*4];
        *(float4*)&sW[row*K3_SBS + q*4] = *(const float4*)src;
    }
    for (int j = tid; j < 96; j += 256)
        sbias[j] = (j < 48) ? accbo[j] : gyrbo[j-48];

    for (int cc = tid; cc < 64*24; cc += 256) {
        int row = cc / 24, q = cc % 24;
        *(float4*)&sA[row*K3_SAS + q*4] = *(const float4*)&g_att[t0+row][q*4];
    }
    __syncthreads();

    int warp = tid >> 5, lane = tid & 31;
    int g = lane >> 2, t4 = lane & 3;
    int wm = warp & 1, wn = warp >> 1;
    int koff = (wn >= 2) ? 48 : 0;

    float4 acc[2][3];
    #pragma unroll
    for (int mi = 0; mi < 2; mi++)
        #pragma unroll
        for (int ni = 0; ni < 3; ni++)
            acc[mi][ni] = make_float4(0.f,0.f,0.f,0.f);

    #pragma unroll
    for (int kt = 0; kt < 6; kt++) {
        float4 av[2];
        #pragma unroll
        for (int mi = 0; mi < 2; mi++) {
            int r0 = wm*32 + mi*16 + g;
            int kk = koff + kt*8 + t4;
            av[mi].x = sA[r0*K3_SAS + kk];
            av[mi].y = sA[(r0+8)*K3_SAS + kk];
            av[mi].z = sA[r0*K3_SAS + kk + 4];
            av[mi].w = sA[(r0+8)*K3_SAS + kk + 4];
        }
        #pragma unroll
        for (int ni = 0; ni < 3; ni++) {
            int n = wn*24 + ni*8 + g;
            float2 bf;
            bf.x = sW[n*K3_SBS + kt*8 + t4];
            bf.y = sW[n*K3_SBS + kt*8 + t4 + 4];
            mma_tf32(acc[0][ni], av[0], bf);
            mma_tf32(acc[1][ni], av[1], bf);
        }
    }

    #pragma unroll
    for (int mi = 0; mi < 2; mi++) {
        #pragma unroll
        for (int ni = 0; ni < 3; ni++) {
            int m0 = wm*32 + mi*16 + g;
            int n  = wn*24 + ni*8 + t4*2;
            float b0 = sbias[n], b1 = sbias[n+1];
            *(float2*)&sPj[m0*K3_SPS + n]     = make_float2(acc[mi][ni].x + b0, acc[mi][ni].y + b1);
            *(float2*)&sPj[(m0+8)*K3_SPS + n] = make_float2(acc[mi][ni].z + b0, acc[mi][ni].w + b1);
        }
    }
    __syncthreads();

    for (int tt = 0; tt < 8; tt++) {
        int tl = warp*8 + tt;
        int t  = t0 + tl;
        float xv[6];
        float sum = 0.f, sq = 0.f;
        #pragma unroll
        for (int i = 0; i < 6; i++) {
            int f = lane + i*32;
            float cv;
            if (f < 48)       cv = sPj[tl*K3_SPS + f];
            else if (f < 144) cv = g_conv[t][f-48];
            else              cv = sPj[tl*K3_SPS + f - 96];
            float x1 = cv + x[(size_t)t*EE + f];
            xv[i] = x1; sum += x1; sq += x1*x1;
        }
        #pragma unroll
        for (int o = 16; o > 0; o >>= 1) {
            sum += __shfl_xor_sync(0xffffffffu, sum, o);
            sq  += __shfl_xor_sync(0xffffffffu, sq,  o);
        }
        float mean = sum * (1.f/192.f);
        float var  = sq * (1.f/192.f) - mean*mean;
        float rstd = rsqrtf(var + 1e-6f);
        #pragma unroll
        for (int i = 0; i < 6; i++) {
            int f = lane + i*32;
            g_x1[t][f]  = xv[i];
            g_x1n[t][f] = (xv[i] - mean) * rstd * ln2g[f] + ln2b[f];
        }
    }
}

// ---------------- Fused MLP: out = x1 + relu(relu(x1n@w1^T+b1)@w2^T+b2) ------
// h [64][388] lives entirely in smem; w1/w2 streamed via double-buffered cp.async.
#define FM_SH_ST 388
#define FM_SX_ST 196
#define FM_W_ST  68
#define FM_SCR   (64*FM_SH_ST)                   // 24832 floats
#define FM_SMEM  ((FM_SCR + 2*192*FM_W_ST) * 4)  // 203776 B

__global__ __launch_bounds__(256) void fused_mlp(
    const float* __restrict__ Xn,
    const float* __restrict__ W1, const float* __restrict__ B1,
    const float* __restrict__ W2, const float* __restrict__ B2,
    const float* __restrict__ X1, float* __restrict__ Out)
{
    extern __shared__ float fsm[];
    float* sH  = fsm;                        // [64][388]
    float* sX  = fsm + FM_SCR;               // phase A: [64][196]
    float* sW1 = sX + 64*FM_SX_ST;           // phase A: 2 x [96][68]
    float* sW2 = fsm + FM_SCR;               // phase B: 2 x [192][68]
    unsigned int sXu  = (unsigned int)__cvta_generic_to_shared(sX);
    unsigned int sW1u = (unsigned int)__cvta_generic_to_shared(sW1);
    unsigned int sW2u = (unsigned int)__cvta_generic_to_shared(sW2);

    int tid = threadIdx.x;
    int t0 = blockIdx.x * 64;
    int warp = tid >> 5, lane = tid & 31;
    int g = lane >> 2, t4 = lane & 3;
    int wm = warp & 1, wn = warp >> 1;

    // prologue: sX tile + w1 stages 0,1
    #pragma unroll
    for (int p = 0; p < 12; p++) {
        int c = tid + p*256;
        int row = c / 48, off = (c % 48) * 4;
        cpa16(sXu + (unsigned int)((row*FM_SX_ST + off)*4),
              Xn + (size_t)(t0+row)*192 + off);
    }
    #pragma unroll
    for (int s = 0; s < 2; s++) {
        #pragma unroll
        for (int p = 0; p < 6; p++) {
            int c = tid + p*256;
            int row = c >> 4, off = (c & 15) * 4;
            cpa16(sW1u + (unsigned int)((s*96*FM_W_ST + row*FM_W_ST + off)*4),
                  W1 + (size_t)((s/3)*96 + row)*192 + (s%3)*64 + off);
        }
        asm volatile("cp.async.commit_group;" ::: "memory");
    }

    // phase A
    float4 acc[2][3];
    for (int s = 0; s < 12; s++) {
        int nc = s / 3, kc = s % 3;
        if (kc == 0) {
            #pragma unroll
            for (int mi = 0; mi < 2; mi++)
                #pragma unroll
                for (int ni = 0; ni < 3; ni++)
                    acc[mi][ni] = make_float4(0.f,0.f,0.f,0.f);
        }
        if (s + 1 < 12) asm volatile("cp.async.wait_group 1;" ::: "memory");
        else            asm volatile("cp.async.wait_group 0;" ::: "memory");
        __syncthreads();

        const float* wbuf = sW1 + (s & 1)*96*FM_W_ST;
        #pragma unroll
        for (int kt = 0; kt < 8; kt++) {
            int kk = kt*8 + t4;
            float4 av[2];
            #pragma unroll
            for (int mi = 0; mi < 2; mi++) {
                int r0 = wm*32 + mi*16 + g;
                av[mi].x = sX[r0*FM_SX_ST + kc*64 + kk];
                av[mi].y = sX[(r0+8)*FM_SX_ST + kc*64 + kk];
                av[mi].z = sX[r0*FM_SX_ST + kc*64 + kk + 4];
                av[mi].w = sX[(r0+8)*FM_SX_ST + kc*64 + kk + 4];
            }
            #pragma unroll
            for (int ni = 0; ni < 3; ni++) {
                int n = wn*24 + ni*8 + g;
                float2 bf;
                bf.x = wbuf[n*FM_W_ST + kk];
                bf.y = wbuf[n*FM_W_ST + kk + 4];
                mma_tf32(acc[0][ni], av[0], bf);
                mma_tf32(acc[1][ni], av[1], bf);
            }
        }

        if (s + 2 < 12) {
            __syncthreads();
            int s2 = s + 2;
            #pragma unroll
            for (int p = 0; p < 6; p++) {
                int c = tid + p*256;
                int row = c >> 4, off = (c & 15) * 4;
                cpa16(sW1u + (unsigned int)(((s & 1)*96*FM_W_ST + row*FM_W_ST + off)*4),
                      W1 + (size_t)((s2/3)*96 + row)*192 + (s2%3)*64 + off);
            }
            asm volatile("cp.async.commit_group;" ::: "memory");
        }

        if (kc == 2) {
            #pragma unroll
            for (int mi = 0; mi < 2; mi++) {
                #pragma unroll
                for (int ni = 0; ni < 3; ni++) {
                    int m0 = wm*32 + mi*16 + g;
                    int n  = nc*96 + wn*24 + ni*8 + t4*2;
                    float b0 = B1[n], b1v = B1[n+1];
                    *(float2*)&sH[m0*FM_SH_ST + n] =
                        make_float2(fmaxf(acc[mi][ni].x + b0, 0.f),
                                    fmaxf(acc[mi][ni].y + b1v, 0.f));
                    *(float2*)&sH[(m0+8)*FM_SH_ST + n] =
                        make_float2(fmaxf(acc[mi][ni].z + b0, 0.f),
                                    fmaxf(acc[mi][ni].w + b1v, 0.f));
                }
            }
        }
    }

    __syncthreads();

    // phase B prologue: w2 stages 0,1
    #pragma unroll
    for (int s = 0; s < 2; s++) {
        #pragma unroll
        for (int p = 0; p < 12; p++) {
            int c = tid + p*256;
            int row = c >> 4, off = (c & 15) * 4;
            cpa16(sW2u + (unsigned int)((s*192*FM_W_ST + row*FM_W_ST + off)*4),
                  W2 + (size_t)row*384 + s*64 + off);
        }
        asm volatile("cp.async.commit_group;" ::: "memory");
    }

    float4 acc2[2][6];
    #pragma unroll
    for (int mi = 0; mi < 2; mi++)
        #pragma unroll
        for (int ni = 0; ni < 6; ni++)
            acc2[mi][ni] = make_float4(0.f,0.f,0.f,0.f);

    for (int s = 0; s < 6; s++) {
        if (s + 1 < 6) asm volatile("cp.async.wait_group 1;" ::: "memory");
        else           asm volatile("cp.async.wait_group 0;" ::: "memory");
        __syncthreads();

        const float* wbuf = sW2 + (s & 1)*192*FM_W_ST;
        #pragma unroll
        for (int kt = 0; kt < 8; kt++) {
            int kk = kt*8 + t4;
            float4 av[2];
            #pragma unroll
            for (int mi = 0; mi < 2; mi++) {
                int r0 = wm*32 + mi*16 + g;
                av[mi].x = sH[r0*FM_SH_ST + s*64 + kk];
                av[mi].y = sH[(r0+8)*FM_SH_ST + s*64 + kk];
                av[mi].z = sH[r0*FM_SH_ST + s*64 + kk + 4];
                av[mi].w = sH[(r0+8)*FM_SH_ST + s*64 + kk + 4];
            }
            #pragma unroll
            for (int ni = 0; ni < 6; ni++) {
                int n = wn*48 + ni*8 + g;
                float2 bf;
                bf.x = wbuf[n*FM_W_ST + kk];
                bf.y = wbuf[n*FM_W_ST + kk + 4];
                mma_tf32(acc2[0][ni], av[0], bf);
                mma_tf32(acc2[1][ni], av[1], bf);
            }
        }

        if (s + 2 < 6) {
            __syncthreads();
            int s2 = s + 2;
            #pragma unroll
            for (int p = 0; p < 12; p++) {
                int c = tid + p*256;
                int row = c >> 4, off = (c & 15) * 4;
                cpa16(sW2u + (unsigned int)(((s & 1)*192*FM_W_ST + row*FM_W_ST + off)*4),
                      W2 + (size_t)row*384 + s2*64 + off);
            }
            asm volatile("cp.async.commit_group;" ::: "memory");
        }
    }

    #pragma unroll
    for (int mi = 0; mi < 2; mi++) {
        #pragma unroll
        for (int ni = 0; ni < 6; ni++) {
            int m0 = t0 + wm*32 + mi*16 + g;
            int n  = wn*48 + ni*8 + t4*2;
            float b0 = B2[n], b1v = B2[n+1];
            {
                float2 v;
                v.x = fmaxf(acc2[mi][ni].x + b0, 0.f) + X1[(size_t)m0*192 + n];
                v.y = fmaxf(acc2[mi][ni].y + b1v, 0.f) + X1[(size_t)m0*192 + n + 1];
                *(float2*)&Out[(size_t)m0*192 + n] = v;
            }
            {
                int m1 = m0 + 8;
                float2 v;
                v.x = fmaxf(acc2[mi][ni].z + b0, 0.f) + X1[(size_t)m1*192 + n];
                v.y = fmaxf(acc2[mi][ni].w + b1v, 0.f) + X1[(size_t)m1*192 + n + 1];
                *(float2*)&Out[(size_t)m1*192 + n] = v;
            }
        }
    }
}

// ---------------- launcher ----------------------------------------------------
extern "C" void kernel_launch(void* const* d_in, const int* in_sizes, int n_in,
                              void* d_out, int out_size)
{
    const float* x     = (const float*)d_in[0];
    const float* ln1g  = (const float*)d_in[1];
    const float* ln1b  = (const float*)d_in[2];
    const float* accw  = (const float*)d_in[3];
    const float* accb  = (const float*)d_in[4];
    const float* accwo = (const float*)d_in[5];
    const float* accbo = (const float*)d_in[6];
    const float* gyrw  = (const float*)d_in[7];
    const float* gyrb  = (const float*)d_in[8];
    const float* gyrwo = (const float*)d_in[9];
    const float* gyrbo = (const float*)d_in[10];
    const float* convw = (const float*)d_in[11];
    const float* ln2g  = (const float*)d_in[12];
    const float* ln2b  = (const float*)d_in[13];
    const float* w1    = (const float*)d_in[14];
    const float* b1    = (const float*)d_in[15];
    const float* w2    = (const float*)d_in[16];
    const float* b2    = (const float*)d_in[17];
    float* out = (float*)d_out;

    cudaFuncSetAttribute(k1b_qkv_mma,     cudaFuncAttributeMaxDynamicSharedMemorySize, K1B_SMEM);
    cudaFuncSetAttribute(k2_attn_mma,     cudaFuncAttributeMaxDynamicSharedMemorySize, K2_SMEM);
    cudaFuncSetAttribute(k3_proj_ln2_mma, cudaFuncAttributeMaxDynamicSharedMemorySize, K3_SMEM);
    cudaFuncSetAttribute(fused_mlp,       cudaFuncAttributeMaxDynamicSharedMemorySize, FM_SMEM);

    void *p_x1, *p_x1n;
    cudaGetSymbolAddress(&p_x1,  g_x1);
    cudaGetSymbolAddress(&p_x1n, g_x1n);

    k1_ln_conv<<<TT/8, 256>>>(x, ln1g, ln1b, convw);
    k1b_qkv_mma<<<TT/64, 256, K1B_SMEM>>>(accw, accb, gyrw, gyrb);
    k2_attn_mma<<<2*BB*NH*2, 256, K2_SMEM>>>();
    k3_proj_ln2_mma<<<TT/64, 256, K3_SMEM>>>(x, accwo, accbo, gyrwo, gyrbo, ln2g, ln2b);
    fused_mlp<<<TT/64, 256, FM_SMEM>>>(
        (const float*)p_x1n, w1, b1, w2, b2, (const float*)p_x1, out);
}

// round 17
// speedup vs baseline: 1.0217x; 1.0217x over previous
#include <cuda_runtime.h>
#include <cstdint>
#include <math.h>

#define BB 128
#define SS 512
#define EE 192
#define TT (BB*SS)
#define QD 48
#define NH 3
#define HD 16

__device__ float g_xn[TT][EE];
__device__ float g_qkv[2][TT][144];
__device__ float g_conv[TT][96];
__device__ float g_att[TT][96];
__device__ float g_x1[TT][EE];
__device__ float g_x1n[TT][EE];
__device__ float g_h[TT][384];

__device__ __forceinline__ unsigned f2tf32(float v) {
    unsigned u;
    asm("cvt.rna.tf32.f32 %0, %1;" : "=r"(u) : "f"(v));
    return u;
}
__device__ __forceinline__ float tf32f(float v) { return __uint_as_float(f2tf32(v)); }

__device__ __forceinline__ float ex2_approx(float v) {
    float r;
    asm("ex2.approx.f32 %0, %1;" : "=f"(r) : "f"(v));
    return r;
}

__device__ __forceinline__ void mma_tf32(float4& c, const float4& a, const float2& b) {
    asm volatile(
        "mma.sync.aligned.m16n8k8.row.col.f32.tf32.tf32.f32 "
        "{%0,%1,%2,%3},{%4,%5,%6,%7},{%8,%9},{%0,%1,%2,%3};"
        : "+f"(c.x), "+f"(c.y), "+f"(c.z), "+f"(c.w)
        : "r"(__float_as_uint(a.x)), "r"(__float_as_uint(a.y)),
          "r"(__float_as_uint(a.z)), "r"(__float_as_uint(a.w)),
          "r"(__float_as_uint(b.x)), "r"(__float_as_uint(b.y)));
}

__device__ __forceinline__ void cpa16(unsigned int dst, const void* src) {
    asm volatile("cp.async.cg.shared.global [%0], [%1], 16;" :: "r"(dst), "l"(src) : "memory");
}

// ---------------- K1: LN1 + feature-conv ----------------
__global__ __launch_bounds__(256) void k1_ln_conv(
    const float* __restrict__ x,
    const float* __restrict__ ln1g, const float* __restrict__ ln1b,
    const float* __restrict__ convw)
{
    __shared__ float sx[8][192];

    int tid = threadIdx.x;
    int warp = tid >> 5, lane = tid & 31;
    int t = blockIdx.x * 8 + warp;

    float v[6];
    float sum = 0.f, sq = 0.f;
    #pragma unroll
    for (int i = 0; i < 6; i++) {
        v[i] = x[(size_t)t*EE + lane + i*32];
        sum += v[i]; sq += v[i]*v[i];
    }
    #pragma unroll
    for (int o = 16; o > 0; o >>= 1) {
        sum += __shfl_xor_sync(0xffffffffu, sum, o);
        sq  += __shfl_xor_sync(0xffffffffu, sq,  o);
    }
    float mean = sum * (1.f/192.f);
    float var  = sq * (1.f/192.f) - mean*mean;
    float rstd = rsqrtf(var + 1e-6f);
    #pragma unroll
    for (int i = 0; i < 6; i++) {
        int f = lane + i*32;
        float xn = (v[i] - mean) * rstd * ln1g[f] + ln1b[f];
        sx[warp][f] = xn;
        g_xn[t][f] = xn;
    }
    __syncwarp();

    int c = t & 3;
    float cw[15];
    #pragma unroll
    for (int k = 0; k < 15; k++) cw[k] = convw[c*15 + k];
    const float* xw = &sx[warp][48];
    #pragma unroll
    for (int r = 0; r < 3; r++) {
        int w = lane + r*32;
        float acc = 0.f;
        #pragma unroll
        for (int k = 0; k < 15; k++) {
            int idx = w + k - 7;
            if (idx >= 0 && idx < 96) acc += cw[k] * xw[idx];
        }
        g_conv[t][w] = acc;
    }
}

// ---------------- K1b: QKV via tf32 mma ----------------
#define K1B_SAS 100
#define K1B_SBS 52
#define K1B_SMEM ((64*K1B_SAS + 288*K1B_SBS + 288) * 4)

__global__ __launch_bounds__(256) void k1b_qkv_mma(
    const float* __restrict__ accw, const float* __restrict__ accb,
    const float* __restrict__ gyrw, const float* __restrict__ gyrb)
{
    extern __shared__ float smm[];
    float* sA    = smm;
    float* sB    = smm + 64*K1B_SAS;
    float* sbias = smm + 64*K1B_SAS + 288*K1B_SBS;

    int tid = threadIdx.x;
    int t0 = blockIdx.x * 64;

    for (int cc = tid; cc < 288*12; cc += 256) {
        int row = cc / 12, q = cc % 12;
        const float* src = (row < 144) ? &accw[row*48 + q*4] : &gyrw[(row-144)*48 + q*4];
        *(float4*)&sB[row*K1B_SBS + q*4] = *(const float4*)src;
    }
    for (int j = tid; j < 288; j += 256)
        sbias[j] = (j < 144) ? accb[j] : gyrb[j-144];

    for (int cc = tid; cc < 64*24; cc += 256) {
        int row = cc / 24, q = cc % 24;
        int srcc = (q < 12) ? q*4 : 96 + (q-12)*4;
        *(float4*)&sA[row*K1B_SAS + q*4] = *(const float4*)&g_xn[t0+row][srcc];
    }
    __syncthreads();

    int warp = tid >> 5, lane = tid & 31;
    int g = lane >> 2, t4 = lane & 3;
    int wm = warp & 1, wn = warp >> 1;
    int koff = (wn >= 2) ? 48 : 0;

    float4 acc[2][9];
    #pragma unroll
    for (int mi = 0; mi < 2; mi++)
        #pragma unroll
        for (int ni = 0; ni < 9; ni++)
            acc[mi][ni] = make_float4(0.f,0.f,0.f,0.f);

    #pragma unroll
    for (int kt = 0; kt < 6; kt++) {
        float4 av[2];
        #pragma unroll
        for (int mi = 0; mi < 2; mi++) {
            int r0 = wm*32 + mi*16 + g;
            int kk = koff + kt*8 + t4;
            av[mi].x = sA[r0*K1B_SAS + kk];
            av[mi].y = sA[(r0+8)*K1B_SAS + kk];
            av[mi].z = sA[r0*K1B_SAS + kk + 4];
            av[mi].w = sA[(r0+8)*K1B_SAS + kk + 4];
        }
        #pragma unroll
        for (int ni = 0; ni < 9; ni++) {
            int n = wn*72 + ni*8 + g;
            float2 bf;
            bf.x = sB[n*K1B_SBS + kt*8 + t4];
            bf.y = sB[n*K1B_SBS + kt*8 + t4 + 4];
            mma_tf32(acc[0][ni], av[0], bf);
            mma_tf32(acc[1][ni], av[1], bf);
        }
    }

    #pragma unroll
    for (int mi = 0; mi < 2; mi++) {
        #pragma unroll
        for (int ni = 0; ni < 9; ni++) {
            int m0 = t0 + wm*32 + mi*16 + g;
            int n  = wn*72 + ni*8 + t4*2;
            int br = (n >= 144);
            int col = n - br*144;
            float b0 = sbias[n], b1 = sbias[n+1];
            *(float2*)&g_qkv[br][m0][col]   = make_float2(acc[mi][ni].x + b0, acc[mi][ni].y + b1);
            *(float2*)&g_qkv[br][m0+8][col] = make_float2(acc[mi][ni].z + b0, acc[mi][ni].w + b1);
        }
    }
}

// ---------------- K2: tensor-core attention (raw-fp32 operands, MUFU exp) ----
#define K2_SMEM ((8192 + 8192 + 8*16*68) * 4)
#define QSCALE (0.25f * 1.44269504088896340736f)

__global__ __launch_bounds__(256) void k2_attn_mma()
{
    extern __shared__ float sm[];
    float* sK = sm;
    float* sV = sm + 8192;
    float* sP = sm + 16384;

    int tid = threadIdx.x;
    int qb   = blockIdx.x & 1;
    int rest = blockIdx.x >> 1;
    int h  = rest % NH;  rest /= NH;
    int b  = rest % BB;
    int br = rest / BB;
    int tbase = b * SS;

    // raw fp32 staging: HMMA.TF32 truncates mantissa in-operand
    for (int idx = tid; idx < SS*HD; idx += 256) {
        int key = idx >> 4, d = idx & 15;
        float kv = g_qkv[br][tbase+key][48 + h*16 + d];
        float vv = g_qkv[br][tbase+key][96 + h*16 + d];
        int laneK = (key & 7)*4 + (d & 3);
        sK[(((key>>3)*2 + (d>>3))*32 + laneK)*2 + ((d>>2)&1)] = kv;
        int laneV = (d & 7)*4 + (key & 3);
        sV[(((key>>3)*2 + (d>>3))*32 + laneV)*2 + ((key>>2)&1)] = vv;
    }

    int wq = tid >> 5, lane = tid & 31;
    int g = lane >> 2, t4 = lane & 3;
    int qbase = tbase + qb*256 + wq*32;

    float4 qa[2][2];
    #pragma unroll
    for (int c = 0; c < 2; c++) {
        const float* qr0 = &g_qkv[br][qbase + c*16 + g][h*16];
        const float* qr1 = &g_qkv[br][qbase + c*16 + g + 8][h*16];
        #pragma unroll
        for (int kt = 0; kt < 2; kt++) {
            qa[c][kt].x = qr0[kt*8 + t4]     * QSCALE;
            qa[c][kt].y = qr1[kt*8 + t4]     * QSCALE;
            qa[c][kt].z = qr0[kt*8 + t4 + 4] * QSCALE;
            qa[c][kt].w = qr1[kt*8 + t4 + 4] * QSCALE;
        }
    }
    __syncthreads();

    float4 oacc[2][2];
    float l0[2], l1[2];
    #pragma unroll
    for (int c = 0; c < 2; c++) {
        oacc[c][0] = make_float4(0.f,0.f,0.f,0.f);
        oacc[c][1] = make_float4(0.f,0.f,0.f,0.f);
        l0[c] = 0.f; l1[c] = 0.f;
    }
    float* sPw = sP + wq*16*68;

    for (int kb = 0; kb < 8; kb++) {
        #pragma unroll
        for (int c = 0; c < 2; c++) {
            float4 sacc[8];
            #pragma unroll
            for (int ni = 0; ni < 8; ni++) sacc[ni] = make_float4(0.f,0.f,0.f,0.f);

            #pragma unroll
            for (int ni = 0; ni < 8; ni++) {
                int nt = kb*8 + ni;
                mma_tf32(sacc[ni], qa[c][0], *(const float2*)&sK[((nt*2+0)*32 + lane)*2]);
                mma_tf32(sacc[ni], qa[c][1], *(const float2*)&sK[((nt*2+1)*32 + lane)*2]);
            }
            #pragma unroll
            for (int ni = 0; ni < 8; ni++) {
                float px = ex2_approx(sacc[ni].x), py = ex2_approx(sacc[ni].y);
                float pz = ex2_approx(sacc[ni].z), pw = ex2_approx(sacc[ni].w);
                l0[c] += px + py; l1[c] += pz + pw;
                *(float2*)&sPw[ g   *68 + ni*8 + 2*t4] = make_float2(px, py);
                *(float2*)&sPw[(g+8)*68 + ni*8 + 2*t4] = make_float2(pz, pw);
            }
            __syncwarp();
            #pragma unroll
            for (int kt2 = 0; kt2 < 8; kt2++) {
                float4 af;
                af.x = sPw[ g   *68 + kt2*8 + t4];
                af.y = sPw[(g+8)*68 + kt2*8 + t4];
                af.z = sPw[ g   *68 + kt2*8 + t4 + 4];
                af.w = sPw[(g+8)*68 + kt2*8 + t4 + 4];
                int ktg = kb*8 + kt2;
                mma_tf32(oacc[c][0], af, *(const float2*)&sV[((ktg*2+0)*32 + lane)*2]);
                mma_tf32(oacc[c][1], af, *(const float2*)&sV[((ktg*2+1)*32 + lane)*2]);
            }
            __syncwarp();
        }
    }

    #pragma unroll
    for (int c = 0; c < 2; c++) {
        float a0 = l0[c], a1 = l1[c];
        a0 += __shfl_xor_sync(0xffffffffu, a0, 1);
        a0 += __shfl_xor_sync(0xffffffffu, a0, 2);
        a1 += __shfl_xor_sync(0xffffffffu, a1, 1);
        a1 += __shfl_xor_sync(0xffffffffu, a1, 2);
        float i0 = 1.f / a0, i1 = 1.f / a1;
        int q0 = qbase + c*16;
        #pragma unroll
        for (int nt = 0; nt < 2; nt++) {
            int col = br*48 + h*16 + nt*8 + 2*t4;
            *(float2*)&g_att[q0+g  ][col] = make_float2(oacc[c][nt].x*i0, oacc[c][nt].y*i0);
            *(float2*)&g_att[q0+g+8][col] = make_float2(oacc[c][nt].z*i1, oacc[c][nt].w*i1);
        }
    }
}

// ---------------- K3: proj mma + concat + res + LN2 ----------------
#define K3_SAS 100
#define K3_SPS 100
#define K3_SBS 52
#define K3_SMEM ((64*K3_SAS + 64*K3_SPS + 96*K3_SBS + 96) * 4)

__global__ __launch_bounds__(256) void k3_proj_ln2_mma(
    const float* __restrict__ x,
    const float* __restrict__ accwo, const float* __restrict__ accbo,
    const float* __restrict__ gyrwo, const float* __restrict__ gyrbo,
    const float* __restrict__ ln2g, const float* __restrict__ ln2b)
{
    extern __shared__ float smm[];
    float* sA    = smm;
    float* sPj   = smm + 64*K3_SAS;
    float* sW    = smm + 64*K3_SAS + 64*K3_SPS;
    float* sbias = sW + 96*K3_SBS;

    int tid = threadIdx.x;
    int t0 = blockIdx.x * 64;

    for (int cc = tid; cc < 96*12; cc += 256) {
        int row = cc / 12, q = cc % 12;
        const float* src = (row < 48) ? &accwo[row*48 + q*4] : &gyrwo[(row-48)*48 + q*4];
        *(float4*)&sW[row*K3_SBS + q*4] = *(const float4*)src;
    }
    for (int j = tid; j < 96; j += 256)
        sbias[j] = (j < 48) ? accbo[j] : gyrbo[j-48];

    for (int cc = tid; cc < 64*24; cc += 256) {
        int row = cc / 24, q = cc % 24;
        *(float4*)&sA[row*K3_SAS + q*4] = *(const float4*)&g_att[t0+row][q*4];
    }
    __syncthreads();

    int warp = tid >> 5, lane = tid & 31;
    int g = lane >> 2, t4 = lane & 3;
    int wm = warp & 1, wn = warp >> 1;
    int koff = (wn >= 2) ? 48 : 0;

    float4 acc[2][3];
    #pragma unroll
    for (int mi = 0; mi < 2; mi++)
        #pragma unroll
        for (int ni = 0; ni < 3; ni++)
            acc[mi][ni] = make_float4(0.f,0.f,0.f,0.f);

    #pragma unroll
    for (int kt = 0; kt < 6; kt++) {
        float4 av[2];
        #pragma unroll
        for (int mi = 0; mi < 2; mi++) {
            int r0 = wm*32 + mi*16 + g;
            int kk = koff + kt*8 + t4;
            av[mi].x = sA[r0*K3_SAS + kk];
            av[mi].y = sA[(r0+8)*K3_SAS + kk];
            av[mi].z = sA[r0*K3_SAS + kk + 4];
            av[mi].w = sA[(r0+8)*K3_SAS + kk + 4];
        }
        #pragma unroll
        for (int ni = 0; ni < 3; ni++) {
            int n = wn*24 + ni*8 + g;
            float2 bf;
            bf.x = sW[n*K3_SBS + kt*8 + t4];
            bf.y = sW[n*K3_SBS + kt*8 + t4 + 4];
            mma_tf32(acc[0][ni], av[0], bf);
            mma_tf32(acc[1][ni], av[1], bf);
        }
    }

    #pragma unroll
    for (int mi = 0; mi < 2; mi++) {
        #pragma unroll
        for (int ni = 0; ni < 3; ni++) {
            int m0 = wm*32 + mi*16 + g;
            int n  = wn*24 + ni*8 + t4*2;
            float b0 = sbias[n], b1 = sbias[n+1];
            *(float2*)&sPj[m0*K3_SPS + n]     = make_float2(acc[mi][ni].x + b0, acc[mi][ni].y + b1);
            *(float2*)&sPj[(m0+8)*K3_SPS + n] = make_float2(acc[mi][ni].z + b0, acc[mi][ni].w + b1);
        }
    }
    __syncthreads();

    for (int tt = 0; tt < 8; tt++) {
        int tl = warp*8 + tt;
        int t  = t0 + tl;
        float xv[6];
        float sum = 0.f, sq = 0.f;
        #pragma unroll
        for (int i = 0; i < 6; i++) {
            int f = lane + i*32;
            float cv;
            if (f < 48)       cv = sPj[tl*K3_SPS + f];
            else if (f < 144) cv = g_conv[t][f-48];
            else              cv = sPj[tl*K3_SPS + f - 96];
            float x1 = cv + x[(size_t)t*EE + f];
            xv[i] = x1; sum += x1; sq += x1*x1;
        }
        #pragma unroll
        for (int o = 16; o > 0; o >>= 1) {
            sum += __shfl_xor_sync(0xffffffffu, sum, o);
            sq  += __shfl_xor_sync(0xffffffffu, sq,  o);
        }
        float mean = sum * (1.f/192.f);
        float var  = sq * (1.f/192.f) - mean*mean;
        float rstd = rsqrtf(var + 1e-6f);
        #pragma unroll
        for (int i = 0; i < 6; i++) {
            int f = lane + i*32;
            g_x1[t][f]  = xv[i];
            g_x1n[t][f] = (xv[i] - mean) * rstd * ln2g[f] + ln2b[f];
        }
    }
}

// ---------------- tf32 GEMM v3: cp.async double-buffered, BK=32 --------------
#define GAS 36
#define G_ABUF (128*GAS)
#define G_BBUF (64*GAS)
#define G_SMEM ((2*G_ABUF + 2*G_BBUF) * 4)

__global__ __launch_bounds__(256) void gemm_tf32_v3(
    const float* __restrict__ A, const float* __restrict__ Bw,
    const float* __restrict__ bias, const float* __restrict__ Res,
    float* __restrict__ C, int N, int K)
{
    extern __shared__ float gsm[];
    float* sA = gsm;
    float* sB = gsm + 2*G_ABUF;
    unsigned int sAu = (unsigned int)__cvta_generic_to_shared(sA);
    unsigned int sBu = (unsigned int)__cvta_generic_to_shared(sB);

    int tid  = threadIdx.x;
    int ms   = blockIdx.x * 128;
    int ns   = blockIdx.y * 64;
    int warp = tid >> 5, lane = tid & 31;
    int wm   = warp & 3;
    int wn   = warp >> 2;
    int g = lane >> 2, t4 = lane & 3;

    float4 acc[2][4];
    #pragma unroll
    for (int mi = 0; mi < 2; mi++)
        #pragma unroll
        for (int ni = 0; ni < 4; ni++)
            acc[mi][ni] = make_float4(0.f,0.f,0.f,0.f);

    int nIter = K >> 5;

    #pragma unroll
    for (int buf = 0; buf < 2; buf++) {
        int k0 = buf * 32;
        #pragma unroll
        for (int p = 0; p < 4; p++) {
            int c = tid + p*256;
            int row = c >> 3, off = (c & 7) * 4;
            cpa16(sAu + (unsigned int)((buf*G_ABUF + row*GAS + off)*4),
                  A + (size_t)(ms+row)*K + k0 + off);
        }
        #pragma unroll
        for (int p = 0; p < 2; p++) {
            int c = tid + p*256;
            int row = c >> 3, off = (c & 7) * 4;
            cpa16(sBu + (unsigned int)((buf*G_BBUF + row*GAS + off)*4),
                  Bw + (size_t)(ns+row)*K + k0 + off);
        }
        asm volatile("cp.async.commit_group;" ::: "memory");
    }

    for (int it = 0; it < nIter; it++) {
        if (it + 1 < nIter) asm volatile("cp.async.wait_group 1;" ::: "memory");
        else                asm volatile("cp.async.wait_group 0;" ::: "memory");
        __syncthreads();

        int buf = it & 1;
        const float* a = sA + buf*G_ABUF;
        const float* bsm = sB + buf*G_BBUF;

        #pragma unroll
        for (int kt = 0; kt < 4; kt++) {
            int kk = kt*8 + t4;
            float4 av[2];
            #pragma unroll
            for (int mi = 0; mi < 2; mi++) {
                int r0 = wm*32 + mi*16 + g;
                av[mi].x = a[r0*GAS + kk];
                av[mi].y = a[(r0+8)*GAS + kk];
                av[mi].z = a[r0*GAS + kk + 4];
                av[mi].w = a[(r0+8)*GAS + kk + 4];
            }
            #pragma unroll
            for (int ni = 0; ni < 4; ni++) {
                int n = wn*32 + ni*8 + g;
                float2 bf;
                bf.x = bsm[n*GAS + kk];
                bf.y = bsm[n*GAS + kk + 4];
                mma_tf32(acc[0][ni], av[0], bf);
                mma_tf32(acc[1][ni], av[1], bf);
            }
        }

        if (it + 2 < nIter) {
            __syncthreads();
            int k0 = (it + 2) * 32;
            #pragma unroll
            for (int p = 0; p < 4; p++) {
                int c = tid + p*256;
                int row = c >> 3, off = (c & 7) * 4;
                cpa16(sAu + (unsigned int)((buf*G_ABUF + row*GAS + off)*4),
                      A + (size_t)(ms+row)*K + k0 + off);
            }
            #pragma unroll
            for (int p = 0; p < 2; p++) {
                int c = tid + p*256;
                int row = c >> 3, off = (c & 7) * 4;
                cpa16(sBu + (unsigned int)((buf*G_BBUF + row*GAS + off)*4),
                      Bw + (size_t)(ns+row)*K + k0 + off);
            }
            asm volatile("cp.async.commit_group;" ::: "memory");
        }
    }

    #pragma unroll
    for (int mi = 0; mi < 2; mi++) {
        #pragma unroll
        for (int ni = 0; ni < 4; ni++) {
            int m0 = ms + wm*32 + mi*16 + g;
            int n  = ns + wn*32 + ni*8 + t4*2;
            float b0 = bias[n], b1 = bias[n+1];
            {
                float2 v;
                v.x = fmaxf(acc[mi][ni].x + b0, 0.f);
                v.y = fmaxf(acc[mi][ni].y + b1, 0.f);
                if (Res) { v.x += Res[(size_t)m0*N + n]; v.y += Res[(size_t)m0*N + n + 1]; }
                *(float2*)&C[(size_t)m0*N + n] = v;
            }
            {
                int m1 = m0 + 8;
                float2 v;
                v.x = fmaxf(acc[mi][ni].z + b0, 0.f);
                v.y = fmaxf(acc[mi][ni].w + b1, 0.f);
                if (Res) { v.x += Res[(size_t)m1*N + n]; v.y += Res[(size_t)m1*N + n + 1]; }
                *(float2*)&C[(size_t)m1*N + n] = v;
            }
        }
    }
}

// ---------------- launcher ----------------------------------------------------
extern "C" void kernel_launch(void* const* d_in, const int* in_sizes, int n_in,
                              void* d_out, int out_size)
{
    const float* x     = (const float*)d_in[0];
    const float* ln1g  = (const float*)d_in[1];
    const float* ln1b  = (const float*)d_in[2];
    const float* accw  = (const float*)d_in[3];
    const float* accb  = (const float*)d_in[4];
    const float* accwo = (const float*)d_in[5];
    const float* accbo = (const float*)d_in[6];
    const float* gyrw  = (const float*)d_in[7];
    const float* gyrb  = (const float*)d_in[8];
    const float* gyrwo = (const float*)d_in[9];
    const float* gyrbo = (const float*)d_in[10];
    const float* convw = (const float*)d_in[11];
    const float* ln2g  = (const float*)d_in[12];
    const float* ln2b  = (const float*)d_in[13];
    const float* w1    = (const float*)d_in[14];
    const float* b1    = (const float*)d_in[15];
    const float* w2    = (const float*)d_in[16];
    const float* b2    = (const float*)d_in[17];
    float* out = (float*)d_out;

    cudaFuncSetAttribute(k1b_qkv_mma,     cudaFuncAttributeMaxDynamicSharedMemorySize, K1B_SMEM);
    cudaFuncSetAttribute(k2_attn_mma,     cudaFuncAttributeMaxDynamicSharedMemorySize, K2_SMEM);
    cudaFuncSetAttribute(k3_proj_ln2_mma, cudaFuncAttributeMaxDynamicSharedMemorySize, K3_SMEM);
    cudaFuncSetAttribute(gemm_tf32_v3,    cudaFuncAttributeMaxDynamicSharedMemorySize, G_SMEM);

    void *p_x1, *p_x1n, *p_h;
    cudaGetSymbolAddress(&p_x1,  g_x1);
    cudaGetSymbolAddress(&p_x1n, g_x1n);
    cudaGetSymbolAddress(&p_h,   g_h);

    k1_ln_conv<<<TT/8, 256>>>(x, ln1g, ln1b, convw);
    k1b_qkv_mma<<<TT/64, 256, K1B_SMEM>>>(accw, accb, gyrw, gyrb);
    k2_attn_mma<<<2*BB*NH*2, 256, K2_SMEM>>>();
    k3_proj_ln2_mma<<<TT/64, 256, K3_SMEM>>>(x, accwo, accbo, gyrwo, gyrbo, ln2g, ln2b);

    gemm_tf32_v3<<<dim3(TT/128, 384/64), 256, G_SMEM>>>(
        (const float*)p_x1n, w1, b1, nullptr, (float*)p_h, 384, 192);
    gemm_tf32_v3<<<dim3(TT/128, 192/64), 256, G_SMEM>>>(
        (const float*)p_h, w2, b2, (const float*)p_x1, out, 192, 384);
}